// round 16
// baseline (speedup 1.0000x reference)
#include <cuda_runtime.h>
#include <cstdint>

// Problem shape (fixed): x [T,B,C,H,W], T=4,B=16,C=512,H=W=32 -> N=1024
#define TT 4
#define BB 16
#define CC 512
#define NN 1024
#define HEADS 8
#define DD 64
#define VTH 1.0f

#define BCN  ((size_t)BB * CC * NN)          // 8,388,608
#define TBCN ((size_t)TT * BB * CC * NN)     // 33,554,432

// ---------------- scratch (static device globals; no runtime allocation) ----
__device__ float g_S[3ull * TBCN];   // spikes q,k,v
__device__ float g_Sa[TBCN];         // attention spikes
__device__ float g_kv[(size_t)TT * BB * HEADS * DD * DD];
__device__ float g_Wt[4ull * CC * CC];   // pre-transposed weights [mat][c][o]

// ===================== helpers =============================================
__device__ __forceinline__ uint32_t smem_u32(const void* p) {
    uint32_t a;
    asm("{ .reg .u64 t; cvta.to.shared.u64 t, %1; cvt.u32.u64 %0, t; }"
        : "=r"(a) : "l"(p));
    return a;
}
__device__ __forceinline__ void cp_async16(uint32_t dst, const void* src) {
    asm volatile("cp.async.cg.shared.global [%0], [%1], 16;"
                 :: "r"(dst), "l"(src));
}
#define CP_COMMIT() asm volatile("cp.async.commit_group;" ::: "memory")
#define CP_WAIT1()  asm volatile("cp.async.wait_group 1;" ::: "memory")
#define CP_WAIT0()  asm volatile("cp.async.wait_group 0;" ::: "memory")

// ---------------------------------------------------------------------------
// W transpose: Wt[mat][c][o] = W[mat][o][c]   (one-shot, 4 MB)
// ---------------------------------------------------------------------------
__global__ void wtrans_kernel(const float* __restrict__ W0, const float* __restrict__ W1,
                              const float* __restrict__ W2, const float* __restrict__ W3)
{
    __shared__ float tile[32][33];
    const int mat = blockIdx.z;
    const float* W = (mat == 0) ? W0 : (mat == 1) ? W1 : (mat == 2) ? W2 : W3;
    const int o0 = blockIdx.x * 32, c0 = blockIdx.y * 32;
    const int t = threadIdx.x;
    const int r = t >> 3, cg = (t & 7) * 4;
    {
        float4 v = *(const float4*)(W + (size_t)(o0 + r) * CC + c0 + cg);
        tile[r][cg + 0] = v.x; tile[r][cg + 1] = v.y;
        tile[r][cg + 2] = v.z; tile[r][cg + 3] = v.w;
    }
    __syncthreads();
    {
        float4 v;
        v.x = tile[cg + 0][r]; v.y = tile[cg + 1][r];
        v.z = tile[cg + 2][r]; v.w = tile[cg + 3][r];
        *(float4*)(g_Wt + (size_t)mat * CC * CC + (size_t)(c0 + r) * CC + o0 + cg) = v;
    }
}

// ---------------------------------------------------------------------------
// Uniform fused conv1x1 GEMM + LIF — round-13 config + PARTIAL x-frag
// prefetch (2 float4 = 8 regs only; W frags are warp-broadcast, left
// in-loop). Scheduling-only change — bit-exact c-sequential accumulation.
// 3-stage rolling cp.async pipeline, tile 128(o) x 128(n), BK=16, 256 thr,
// 8x8 microtile split {lo,hi+64}, 2 CTAs/SM, one __syncthreads/iteration.
// Dynamic smem: Xs 3x[16][128] + Ws 3x[16][128] + Vs[64][256] = 112 KB.
// ---------------------------------------------------------------------------
template <int CONN>
__global__ __launch_bounds__(256, 2)
void gemm_lif(const float* __restrict__ In,
              const float* __restrict__ WtAll, int matofs,
              const float* __restrict__ b0, const float* __restrict__ b1,
              const float* __restrict__ b2,
              const float* __restrict__ xsc,
              float* __restrict__ Out)
{
    extern __shared__ float sm[];
    float* Xs = sm;            // 3 stages x [16][128]
    float* Ws = sm + 6144;     // 3 stages x [16][128]
    float* Vs = sm + 12288;    // [64][256]
    const uint32_t xs_b = smem_u32(Xs), ws_b = smem_u32(Ws);

    const int tid = threadIdx.x, tx = tid & 15, ty = tid >> 4;
    const int z = blockIdx.z;
    const int mat = CONN ? 0 : (z >> 4);
    const int b = CONN ? z : (z & 15);
    const int n0 = blockIdx.x * 128, o0 = blockIdx.y * 128;

    const float* Wt = WtAll + (size_t)(matofs + mat) * CC * CC;
    const float* bias = (mat == 0) ? b0 : (mat == 1) ? b1 : b2;
    float* outb = Out + (CONN ? 0 : (size_t)mat * TBCN);

    float bb[8];
#pragma unroll
    for (int i = 0; i < 4; i++) {
        bb[i] = bias[o0 + ty * 4 + i];
        bb[4 + i] = bias[o0 + 64 + ty * 4 + i];
    }

    const int lr = tid >> 4;           // fill row 0..15
    const int lc = (tid & 15) * 8;     // fill col base (8 floats = 2x16B)

    auto prefetch = [&](int gg, int s) {
        const int tt = gg >> 5;
        const int k0 = (gg & 31) << 4;
        const float* Xb = In + (size_t)(tt * BB + b) * CC * NN;
        const float* xp = Xb + (size_t)(k0 + lr) * NN + n0 + lc;
        uint32_t xd = xs_b + (uint32_t)(s * 2048 + lr * 128 + lc) * 4;
        cp_async16(xd, xp); cp_async16(xd + 16, xp + 4);
        const float* wp = Wt + (size_t)(k0 + lr) * CC + o0 + lc;
        uint32_t wd = ws_b + (uint32_t)(s * 2048 + lr * 128 + lc) * 4;
        cp_async16(wd, wp); cp_async16(wd + 16, wp + 4);
        CP_COMMIT();
    };

    float acc[8][8];
#pragma unroll
    for (int i = 0; i < 8; i++)
#pragma unroll
        for (int j = 0; j < 8; j++) acc[i][j] = 0.f;

    prefetch(0, 0);
    prefetch(1, 1);

    int cur = 0, pf = 2;
    const int NG = TT * 32;  // 128

    for (int g = 0; g < NG; g++) {
        if (g < NG - 1) CP_WAIT1(); else CP_WAIT0();
        __syncthreads();
        if (g + 2 < NG) prefetch(g + 2, pf);

        const float* Xst = Xs + cur * 2048;
        const float* Wst = Ws + cur * 2048;

        // partial software pipeline: prefetch only the X fragments (8 regs)
        float4 xa = *(const float4*)(Xst + tx * 4);
        float4 xc = *(const float4*)(Xst + 64 + tx * 4);
#pragma unroll
        for (int kk = 0; kk < 16; kk++) {
            float4 nxa, nxc;
            if (kk < 15) {
                nxa = *(const float4*)(Xst + (kk + 1) * 128 + tx * 4);
                nxc = *(const float4*)(Xst + (kk + 1) * 128 + 64 + tx * 4);
            }
            float4 wa = *(const float4*)(Wst + kk * 128 + ty * 4);
            float4 wc = *(const float4*)(Wst + kk * 128 + 64 + ty * 4);
            float xv[8] = {xa.x, xa.y, xa.z, xa.w, xc.x, xc.y, xc.z, xc.w};
            float wv[8] = {wa.x, wa.y, wa.z, wa.w, wc.x, wc.y, wc.z, wc.w};
#pragma unroll
            for (int i = 0; i < 8; i++)
#pragma unroll
                for (int j = 0; j < 8; j++)
                    acc[i][j] += wv[i] * xv[j];
            xa = nxa; xc = nxc;
        }

        if ((g & 31) == 31) {
            const int t = g >> 5;
            const size_t tbofs = (size_t)(t * BB + b) * CC * NN;
#pragma unroll
            for (int i = 0; i < 8; i++) {
                const int o = o0 + ((i < 4) ? (ty * 4 + i) : (64 + ty * 4 + i - 4));
                const size_t rowb = tbofs + (size_t)o * NN + n0;
#pragma unroll
                for (int hf = 0; hf < 2; hf++) {
                    const int nc = hf ? (64 + tx * 4) : (tx * 4);
                    float4 xs4;
                    if (CONN) xs4 = *(const float4*)(xsc + rowb + nc);
                    float4 r;
#pragma unroll
                    for (int j = 0; j < 4; j++) {
                        const int vi = i * 8 + hf * 4 + j;
                        float v = (t == 0) ? 0.f : Vs[vi * 256 + tid];
                        float p = acc[i][hf * 4 + j] + bb[i];
                        float chg = CONN ? (p + ((const float*)&xs4)[j]) : p;
                        v = v + (chg - v) * 0.5f;
                        float s = (v >= VTH) ? 1.f : 0.f;
                        Vs[vi * 256 + tid] = (s != 0.f) ? 0.f : v;
                        ((float*)&r)[j] = s;
                    }
                    *(float4*)(outb + rowb + nc) = r;
                }
            }
#pragma unroll
            for (int i = 0; i < 8; i++)
#pragma unroll
                for (int j = 0; j < 8; j++) acc[i][j] = 0.f;
        }

        cur = (cur == 2) ? 0 : cur + 1;
        pf = (pf == 2) ? 0 : pf + 1;
    }
}

// ---------------------------------------------------------------------------
// Fused pack + kv: per (t,b,h) block, ballot-pack K/V spike rows directly
// into smem (batched loads), then kv[d][e] = popc_n(K[d] & V[e]).
// The n->bit map is a shared permutation -> popc counts are bit-exact ints.
// ---------------------------------------------------------------------------
__global__ __launch_bounds__(256)
void kv_pack_pop_kernel()
{
    __shared__ uint32_t Ks[64 * 33];
    __shared__ uint32_t Vt[32 * 68];

    const int tbh = blockIdx.x;
    const int tb = tbh >> 3;
    const int h = tbh & 7;
    const float* Kf = g_S + 1ull * TBCN + ((size_t)tb * CC + h * DD) * NN;
    const float* Vf = g_S + 2ull * TBCN + ((size_t)tb * CC + h * DD) * NN;

    const int tid = threadIdx.x;
    const int wp = tid >> 5, l = tid & 31;

#pragma unroll
    for (int rr = 0; rr < 8; rr++) {
        const int row = wp * 8 + rr;
        const float* kr = Kf + (size_t)row * NN;
        const float* vr = Vf + (size_t)row * NN;
        float4 kf[8], vf[8];
#pragma unroll
        for (int c = 0; c < 8; c++) {
            kf[c] = *(const float4*)(kr + c * 128 + l * 4);
            vf[c] = *(const float4*)(vr + c * 128 + l * 4);
        }
#pragma unroll
        for (int c = 0; c < 8; c++) {
            uint32_t k0 = __ballot_sync(0xFFFFFFFFu, kf[c].x != 0.f);
            uint32_t k1 = __ballot_sync(0xFFFFFFFFu, kf[c].y != 0.f);
            uint32_t k2 = __ballot_sync(0xFFFFFFFFu, kf[c].z != 0.f);
            uint32_t k3 = __ballot_sync(0xFFFFFFFFu, kf[c].w != 0.f);
            uint32_t v0 = __ballot_sync(0xFFFFFFFFu, vf[c].x != 0.f);
            uint32_t v1 = __ballot_sync(0xFFFFFFFFu, vf[c].y != 0.f);
            uint32_t v2 = __ballot_sync(0xFFFFFFFFu, vf[c].z != 0.f);
            uint32_t v3 = __ballot_sync(0xFFFFFFFFu, vf[c].w != 0.f);
            if (l == 0) {
                Ks[row * 33 + c * 4 + 0] = k0;
                Ks[row * 33 + c * 4 + 1] = k1;
                Ks[row * 33 + c * 4 + 2] = k2;
                Ks[row * 33 + c * 4 + 3] = k3;
                Vt[(c * 4 + 0) * 68 + row] = v0;
                Vt[(c * 4 + 1) * 68 + row] = v1;
                Vt[(c * 4 + 2) * 68 + row] = v2;
                Vt[(c * 4 + 3) * 68 + row] = v3;
            }
        }
    }
    __syncthreads();

    const int d = tid >> 2;
    const int eb = (tid & 3) * 16;
    int cnt[16];
#pragma unroll
    for (int i = 0; i < 16; i++) cnt[i] = 0;

#pragma unroll 4
    for (int w = 0; w < 32; w++) {
        const uint32_t kd = Ks[d * 33 + w];
        const uint32_t* vr = &Vt[w * 68 + eb];
#pragma unroll
        for (int g = 0; g < 4; g++) {
            uint4 v4 = *(const uint4*)(vr + g * 4);
            cnt[g * 4 + 0] += __popc(kd & v4.x);
            cnt[g * 4 + 1] += __popc(kd & v4.y);
            cnt[g * 4 + 2] += __popc(kd & v4.z);
            cnt[g * 4 + 3] += __popc(kd & v4.w);
        }
    }

    float* kvout = g_kv + (size_t)tbh * DD * DD + (size_t)d * DD + eb;
#pragma unroll
    for (int g = 0; g < 4; g++) {
        float4 r = {(float)cnt[g * 4 + 0], (float)cnt[g * 4 + 1],
                    (float)cnt[g * 4 + 2], (float)cnt[g * 4 + 3]};
        *(float4*)(kvout + g * 4) = r;
    }
}

// ---------------------------------------------------------------------------
// Fused attention output + LIF — round-13 config verbatim (best measured).
// Block (n-tile 64, bh), loop t; whole kv[64][68] + Q[64][68] tiles in smem;
// 2 barriers per t. d accumulation 0..63 sequential — bit-exact.
// ---------------------------------------------------------------------------
__global__ __launch_bounds__(256)
void attn_lif_kernel()
{
    const int bh = blockIdx.y;
    const int b = bh >> 3;
    const int h = bh & 7;
    const int n0 = blockIdx.x * 64;

    __shared__ __align__(16) float kvs[DD][DD + 4];
    __shared__ __align__(16) float Qs[DD][DD + 4];

    const int tid = threadIdx.x;
    const int tx = tid & 15, ty = tid >> 4;

    float v[4][4];
#pragma unroll
    for (int i = 0; i < 4; i++)
#pragma unroll
        for (int j = 0; j < 4; j++) v[i][j] = 0.f;

    for (int t = 0; t < TT; t++) {
        const int tb = t * BB + b;
        const float* Q_ = g_S + ((size_t)tb * CC + h * DD) * NN;
        const float* kvp = g_kv + (size_t)(t * 128 + bh) * DD * DD;

#pragma unroll
        for (int r = 0; r < 4; r++) {
            int fid = r * 256 + tid;
            int dd = fid >> 4;
            int eg = (fid & 15) * 4;
            float4 vv = *(const float4*)(kvp + (size_t)dd * DD + eg);
            *(float4*)(&kvs[dd][eg]) = vv;
            float4 qv = *(const float4*)(Q_ + (size_t)dd * NN + n0 + eg);
            *(float4*)(&Qs[dd][eg]) = qv;
        }
        __syncthreads();

        float acc[4][4] = {};
#pragma unroll 8
        for (int kk = 0; kk < DD; kk++) {
            float4 qf = *(const float4*)(&Qs[kk][tx * 4]);
            float4 kf = *(const float4*)(&kvs[kk][ty * 4]);
            float qa[4] = {qf.x, qf.y, qf.z, qf.w};
            float ka[4] = {kf.x, kf.y, kf.z, kf.w};
#pragma unroll
            for (int i = 0; i < 4; i++)
#pragma unroll
                for (int j = 0; j < 4; j++)
                    acc[i][j] += ka[i] * qa[j];
        }
        __syncthreads();

#pragma unroll
        for (int i = 0; i < 4; i++) {
            const int e = ty * 4 + i;
            float4 r;
#pragma unroll
            for (int j = 0; j < 4; j++) {
                float xx = acc[i][j] * 0.125f;
                float vv = v[i][j];
                vv = vv + (xx - vv) * 0.5f;
                float s = (vv >= VTH) ? 1.f : 0.f;
                v[i][j] = (s != 0.f) ? 0.f : vv;
                ((float*)&r)[j] = s;
            }
            *(float4*)(g_Sa + ((size_t)tb * CC + h * DD + e) * NN + n0 + tx * 4) = r;
        }
    }
}

// ---------------------------------------------------------------------------
extern "C" void kernel_launch(void* const* d_in, const int* in_sizes, int n_in,
                              void* d_out, int out_size)
{
    const float* x  = (const float*)d_in[0];
    const float* Wq = (const float*)d_in[1];
    const float* bq = (const float*)d_in[2];
    const float* Wk = (const float*)d_in[3];
    const float* bk = (const float*)d_in[4];
    const float* Wv = (const float*)d_in[5];
    const float* bv = (const float*)d_in[6];
    const float* Wp = (const float*)d_in[7];
    const float* bp = (const float*)d_in[8];
    float* out = (float*)d_out;

    void *pS, *pSa, *pWt;
    cudaGetSymbolAddress(&pS, g_S);
    cudaGetSymbolAddress(&pSa, g_Sa);
    cudaGetSymbolAddress(&pWt, g_Wt);

    const int GL_SMEM = (12288 + 16384) * 4;  // 114688 bytes (3 stages + Vs)
    cudaFuncSetAttribute(gemm_lif<0>, cudaFuncAttributeMaxDynamicSharedMemorySize, GL_SMEM);
    cudaFuncSetAttribute(gemm_lif<1>, cudaFuncAttributeMaxDynamicSharedMemorySize, GL_SMEM);

    // 1. one-shot weight transpose (Wt[c][o])
    wtrans_kernel<<<dim3(16, 16, 4), 256>>>(Wq, Wk, Wv, Wp);
    // 2. fused QKV conv GEMM + LIF (q,k,v in one launch; bit-exact chains)
    gemm_lif<0><<<dim3(8, 4, 48), 256, GL_SMEM>>>(
        x, (const float*)pWt, 0, bq, bk, bv, nullptr, (float*)pS);
    // 3. fused pack + kv popcount (bit-exact integer counts)
    kv_pack_pop_kernel<<<TT * BB * HEADS, 256>>>();
    // 4. fused attention output + LIF
    attn_lif_kernel<<<dim3(NN / 64, BB * HEADS), 256>>>();
    // 5. fused proj conv GEMM + connecting LIF -> final spikes
    gemm_lif<1><<<dim3(8, 4, 16), 256, GL_SMEM>>>(
        (const float*)pSa, (const float*)pWt, 3, bp, bp, bp, x, out);
}

// round 17
// speedup vs baseline: 1.0329x; 1.0329x over previous
#include <cuda_runtime.h>
#include <cstdint>

// Problem shape (fixed): x [T,B,C,H,W], T=4,B=16,C=512,H=W=32 -> N=1024
#define TT 4
#define BB 16
#define CC 512
#define NN 1024
#define HEADS 8
#define DD 64
#define VTH 1.0f

#define BCN  ((size_t)BB * CC * NN)          // 8,388,608
#define TBCN ((size_t)TT * BB * CC * NN)     // 33,554,432

// ---------------- scratch (static device globals; no runtime allocation) ----
__device__ float g_S[3ull * TBCN];   // spikes q,k,v
__device__ float g_Sa[TBCN];         // attention spikes
__device__ float g_kv[(size_t)TT * BB * HEADS * DD * DD];
__device__ float g_Wt[4ull * CC * CC];   // pre-transposed weights [mat][c][o]

// ===================== helpers =============================================
__device__ __forceinline__ uint32_t smem_u32(const void* p) {
    uint32_t a;
    asm("{ .reg .u64 t; cvta.to.shared.u64 t, %1; cvt.u32.u64 %0, t; }"
        : "=r"(a) : "l"(p));
    return a;
}
__device__ __forceinline__ void cp_async16(uint32_t dst, const void* src) {
    asm volatile("cp.async.cg.shared.global [%0], [%1], 16;"
                 :: "r"(dst), "l"(src));
}
#define CP_COMMIT() asm volatile("cp.async.commit_group;" ::: "memory")
#define CP_WAIT1()  asm volatile("cp.async.wait_group 1;" ::: "memory")
#define CP_WAIT0()  asm volatile("cp.async.wait_group 0;" ::: "memory")

// ---------------------------------------------------------------------------
// W transpose: Wt[mat][c][o] = W[mat][o][c]   (one-shot, 4 MB)
// ---------------------------------------------------------------------------
__global__ void wtrans_kernel(const float* __restrict__ W0, const float* __restrict__ W1,
                              const float* __restrict__ W2, const float* __restrict__ W3)
{
    __shared__ float tile[32][33];
    const int mat = blockIdx.z;
    const float* W = (mat == 0) ? W0 : (mat == 1) ? W1 : (mat == 2) ? W2 : W3;
    const int o0 = blockIdx.x * 32, c0 = blockIdx.y * 32;
    const int t = threadIdx.x;
    const int r = t >> 3, cg = (t & 7) * 4;
    {
        float4 v = *(const float4*)(W + (size_t)(o0 + r) * CC + c0 + cg);
        tile[r][cg + 0] = v.x; tile[r][cg + 1] = v.y;
        tile[r][cg + 2] = v.z; tile[r][cg + 3] = v.w;
    }
    __syncthreads();
    {
        float4 v;
        v.x = tile[cg + 0][r]; v.y = tile[cg + 1][r];
        v.z = tile[cg + 2][r]; v.w = tile[cg + 3][r];
        *(float4*)(g_Wt + (size_t)mat * CC * CC + (size_t)(c0 + r) * CC + o0 + cg) = v;
    }
}

// ---------------------------------------------------------------------------
// Uniform fused conv1x1 GEMM + LIF — round-13 config VERBATIM (frozen):
// 3-stage rolling cp.async pipeline, tile 128(o) x 128(n), BK=16, 256 thr,
// 8x8 microtile split {lo,hi+64}, 2 CTAs/SM, one __syncthreads/iteration.
// Per-output accumulation sequential over c — bit-exact vs reference chain.
// Dynamic smem: Xs 3x[16][128] + Ws 3x[16][128] + Vs[64][256] = 112 KB.
// ---------------------------------------------------------------------------
template <int CONN>
__global__ __launch_bounds__(256, 2)
void gemm_lif(const float* __restrict__ In,
              const float* __restrict__ WtAll, int matofs,
              const float* __restrict__ b0, const float* __restrict__ b1,
              const float* __restrict__ b2,
              const float* __restrict__ xsc,
              float* __restrict__ Out)
{
    extern __shared__ float sm[];
    float* Xs = sm;            // 3 stages x [16][128]
    float* Ws = sm + 6144;     // 3 stages x [16][128]
    float* Vs = sm + 12288;    // [64][256]
    const uint32_t xs_b = smem_u32(Xs), ws_b = smem_u32(Ws);

    const int tid = threadIdx.x, tx = tid & 15, ty = tid >> 4;
    const int z = blockIdx.z;
    const int mat = CONN ? 0 : (z >> 4);
    const int b = CONN ? z : (z & 15);
    const int n0 = blockIdx.x * 128, o0 = blockIdx.y * 128;

    const float* Wt = WtAll + (size_t)(matofs + mat) * CC * CC;
    const float* bias = (mat == 0) ? b0 : (mat == 1) ? b1 : b2;
    float* outb = Out + (CONN ? 0 : (size_t)mat * TBCN);

    float bb[8];
#pragma unroll
    for (int i = 0; i < 4; i++) {
        bb[i] = bias[o0 + ty * 4 + i];
        bb[4 + i] = bias[o0 + 64 + ty * 4 + i];
    }

    const int lr = tid >> 4;           // fill row 0..15
    const int lc = (tid & 15) * 8;     // fill col base (8 floats = 2x16B)

    auto prefetch = [&](int gg, int s) {
        const int tt = gg >> 5;
        const int k0 = (gg & 31) << 4;
        const float* Xb = In + (size_t)(tt * BB + b) * CC * NN;
        const float* xp = Xb + (size_t)(k0 + lr) * NN + n0 + lc;
        uint32_t xd = xs_b + (uint32_t)(s * 2048 + lr * 128 + lc) * 4;
        cp_async16(xd, xp); cp_async16(xd + 16, xp + 4);
        const float* wp = Wt + (size_t)(k0 + lr) * CC + o0 + lc;
        uint32_t wd = ws_b + (uint32_t)(s * 2048 + lr * 128 + lc) * 4;
        cp_async16(wd, wp); cp_async16(wd + 16, wp + 4);
        CP_COMMIT();
    };

    float acc[8][8];
#pragma unroll
    for (int i = 0; i < 8; i++)
#pragma unroll
        for (int j = 0; j < 8; j++) acc[i][j] = 0.f;

    prefetch(0, 0);
    prefetch(1, 1);

    int cur = 0, pf = 2;
    const int NG = TT * 32;  // 128

    for (int g = 0; g < NG; g++) {
        if (g < NG - 1) CP_WAIT1(); else CP_WAIT0();
        __syncthreads();
        if (g + 2 < NG) prefetch(g + 2, pf);

        const float* Xst = Xs + cur * 2048;
        const float* Wst = Ws + cur * 2048;
#pragma unroll
        for (int kk = 0; kk < 16; kk++) {
            float4 xa = *(const float4*)(Xst + kk * 128 + tx * 4);
            float4 xc = *(const float4*)(Xst + kk * 128 + 64 + tx * 4);
            float4 wa = *(const float4*)(Wst + kk * 128 + ty * 4);
            float4 wc = *(const float4*)(Wst + kk * 128 + 64 + ty * 4);
            float xv[8] = {xa.x, xa.y, xa.z, xa.w, xc.x, xc.y, xc.z, xc.w};
            float wv[8] = {wa.x, wa.y, wa.z, wa.w, wc.x, wc.y, wc.z, wc.w};
#pragma unroll
            for (int i = 0; i < 8; i++)
#pragma unroll
                for (int j = 0; j < 8; j++)
                    acc[i][j] += wv[i] * xv[j];
        }

        if ((g & 31) == 31) {
            const int t = g >> 5;
            const size_t tbofs = (size_t)(t * BB + b) * CC * NN;
#pragma unroll
            for (int i = 0; i < 8; i++) {
                const int o = o0 + ((i < 4) ? (ty * 4 + i) : (64 + ty * 4 + i - 4));
                const size_t rowb = tbofs + (size_t)o * NN + n0;
#pragma unroll
                for (int hf = 0; hf < 2; hf++) {
                    const int nc = hf ? (64 + tx * 4) : (tx * 4);
                    float4 xs4;
                    if (CONN) xs4 = *(const float4*)(xsc + rowb + nc);
                    float4 r;
#pragma unroll
                    for (int j = 0; j < 4; j++) {
                        const int vi = i * 8 + hf * 4 + j;
                        float v = (t == 0) ? 0.f : Vs[vi * 256 + tid];
                        float p = acc[i][hf * 4 + j] + bb[i];
                        float chg = CONN ? (p + ((const float*)&xs4)[j]) : p;
                        v = v + (chg - v) * 0.5f;
                        float s = (v >= VTH) ? 1.f : 0.f;
                        Vs[vi * 256 + tid] = (s != 0.f) ? 0.f : v;
                        ((float*)&r)[j] = s;
                    }
                    *(float4*)(outb + rowb + nc) = r;
                }
            }
#pragma unroll
            for (int i = 0; i < 8; i++)
#pragma unroll
                for (int j = 0; j < 8; j++) acc[i][j] = 0.f;
        }

        cur = (cur == 2) ? 0 : cur + 1;
        pf = (pf == 2) ? 0 : pf + 1;
    }
}

// ---------------------------------------------------------------------------
// Fused pack + kv (round-13 verbatim): ballot-pack K/V spike rows into smem,
// then kv[d][e] = popc_n(K[d] & V[e]) — bit-exact integer counts.
// ---------------------------------------------------------------------------
__global__ __launch_bounds__(256)
void kv_pack_pop_kernel()
{
    __shared__ uint32_t Ks[64 * 33];
    __shared__ uint32_t Vt[32 * 68];

    const int tbh = blockIdx.x;
    const int tb = tbh >> 3;
    const int h = tbh & 7;
    const float* Kf = g_S + 1ull * TBCN + ((size_t)tb * CC + h * DD) * NN;
    const float* Vf = g_S + 2ull * TBCN + ((size_t)tb * CC + h * DD) * NN;

    const int tid = threadIdx.x;
    const int wp = tid >> 5, l = tid & 31;

#pragma unroll
    for (int rr = 0; rr < 8; rr++) {
        const int row = wp * 8 + rr;
        const float* kr = Kf + (size_t)row * NN;
        const float* vr = Vf + (size_t)row * NN;
        float4 kf[8], vf[8];
#pragma unroll
        for (int c = 0; c < 8; c++) {
            kf[c] = *(const float4*)(kr + c * 128 + l * 4);
            vf[c] = *(const float4*)(vr + c * 128 + l * 4);
        }
#pragma unroll
        for (int c = 0; c < 8; c++) {
            uint32_t k0 = __ballot_sync(0xFFFFFFFFu, kf[c].x != 0.f);
            uint32_t k1 = __ballot_sync(0xFFFFFFFFu, kf[c].y != 0.f);
            uint32_t k2 = __ballot_sync(0xFFFFFFFFu, kf[c].z != 0.f);
            uint32_t k3 = __ballot_sync(0xFFFFFFFFu, kf[c].w != 0.f);
            uint32_t v0 = __ballot_sync(0xFFFFFFFFu, vf[c].x != 0.f);
            uint32_t v1 = __ballot_sync(0xFFFFFFFFu, vf[c].y != 0.f);
            uint32_t v2 = __ballot_sync(0xFFFFFFFFu, vf[c].z != 0.f);
            uint32_t v3 = __ballot_sync(0xFFFFFFFFu, vf[c].w != 0.f);
            if (l == 0) {
                Ks[row * 33 + c * 4 + 0] = k0;
                Ks[row * 33 + c * 4 + 1] = k1;
                Ks[row * 33 + c * 4 + 2] = k2;
                Ks[row * 33 + c * 4 + 3] = k3;
                Vt[(c * 4 + 0) * 68 + row] = v0;
                Vt[(c * 4 + 1) * 68 + row] = v1;
                Vt[(c * 4 + 2) * 68 + row] = v2;
                Vt[(c * 4 + 3) * 68 + row] = v3;
            }
        }
    }
    __syncthreads();

    const int d = tid >> 2;
    const int eb = (tid & 3) * 16;
    int cnt[16];
#pragma unroll
    for (int i = 0; i < 16; i++) cnt[i] = 0;

#pragma unroll 4
    for (int w = 0; w < 32; w++) {
        const uint32_t kd = Ks[d * 33 + w];
        const uint32_t* vr = &Vt[w * 68 + eb];
#pragma unroll
        for (int g = 0; g < 4; g++) {
            uint4 v4 = *(const uint4*)(vr + g * 4);
            cnt[g * 4 + 0] += __popc(kd & v4.x);
            cnt[g * 4 + 1] += __popc(kd & v4.y);
            cnt[g * 4 + 2] += __popc(kd & v4.z);
            cnt[g * 4 + 3] += __popc(kd & v4.w);
        }
    }

    float* kvout = g_kv + (size_t)tbh * DD * DD + (size_t)d * DD + eb;
#pragma unroll
    for (int g = 0; g < 4; g++) {
        float4 r = {(float)cnt[g * 4 + 0], (float)cnt[g * 4 + 1],
                    (float)cnt[g * 4 + 2], (float)cnt[g * 4 + 3]};
        *(float4*)(kvout + g * 4) = r;
    }
}

// ---------------------------------------------------------------------------
// Fused attention output + LIF — cp.async tile fills, Q DOUBLE-BUFFERED:
// Q(t+1) loads overlap compute(t); kv(t) load overlaps epilogue(t-1).
// Canonical cp.async sync: wait_group -> __syncthreads -> read.
// smem: kvs [64][68] + Qs 2x[64][68] = 52 KB (reg-limited 4 CTAs unchanged).
// d accumulation 0..63 sequential per output — bit-exact.
// ---------------------------------------------------------------------------
__global__ __launch_bounds__(256)
void attn_lif_kernel()
{
    __shared__ __align__(16) float kvs[DD][DD + 4];
    __shared__ __align__(16) float Qs[2][DD][DD + 4];

    const int bh = blockIdx.y;
    const int b = bh >> 3;
    const int h = bh & 7;
    const int n0 = blockIdx.x * 64;

    const int tid = threadIdx.x;
    const int tx = tid & 15, ty = tid >> 4;
    const uint32_t kv_b = smem_u32(&kvs[0][0]);
    const uint32_t q_b0 = smem_u32(&Qs[0][0][0]);
    const uint32_t q_b1 = smem_u32(&Qs[1][0][0]);

    // per-thread fill chunks: 4 x 16B per array (1024 chunks / 256 threads)
    auto issue_kv = [&](int t) {
        const float* kvp = g_kv + (size_t)(t * 128 + bh) * DD * DD;
#pragma unroll
        for (int q = 0; q < 4; q++) {
            const int cid = q * 256 + tid;
            const int row = cid >> 4, col = cid & 15;
            cp_async16(kv_b + (uint32_t)(row * 272 + col * 16),
                       kvp + (size_t)row * DD + col * 4);
        }
    };
    auto issue_q = [&](int t) {
        const float* Q_ = g_S + ((size_t)(t * BB + b) * CC + h * DD) * NN + n0;
        const uint32_t qb = (t & 1) ? q_b1 : q_b0;
#pragma unroll
        for (int q = 0; q < 4; q++) {
            const int cid = q * 256 + tid;
            const int row = cid >> 4, col = cid & 15;
            cp_async16(qb + (uint32_t)(row * 272 + col * 16),
                       Q_ + (size_t)row * NN + col * 4);
        }
    };

    float v[4][4];
#pragma unroll
    for (int i = 0; i < 4; i++)
#pragma unroll
        for (int j = 0; j < 4; j++) v[i][j] = 0.f;

    float pacc[4][4];   // previous t's acc, for epilogue overlap
    int have_prev = 0;

    // prologue: kv0 + Q0 in one group
    issue_kv(0); issue_q(0); CP_COMMIT();

    for (int t = 0; t < TT; t++) {
        if (t > 0) { issue_kv(t); CP_COMMIT(); }

        // epilogue for t-1 (global stores; overlaps kv(t) load)
        if (have_prev) {
            const int ptb = (t - 1) * BB + b;
#pragma unroll
            for (int i = 0; i < 4; i++) {
                const int e = ty * 4 + i;
                float4 r;
#pragma unroll
                for (int j = 0; j < 4; j++) {
                    float xx = pacc[i][j] * 0.125f;
                    float vv = v[i][j];
                    vv = vv + (xx - vv) * 0.5f;
                    float s = (vv >= VTH) ? 1.f : 0.f;
                    v[i][j] = (s != 0.f) ? 0.f : vv;
                    ((float*)&r)[j] = s;
                }
                *(float4*)(g_Sa + ((size_t)ptb * CC + h * DD + e) * NN + n0 + tx * 4) = r;
            }
        }

        if (t + 1 < TT) { issue_q(t + 1); CP_COMMIT(); CP_WAIT1(); }
        else            { CP_WAIT0(); }
        __syncthreads();

        float acc[4][4] = {};
        const float (*Qb)[DD + 4] = Qs[t & 1];
#pragma unroll 8
        for (int kk = 0; kk < DD; kk++) {
            float4 qf = *(const float4*)(&Qb[kk][tx * 4]);
            float4 kf = *(const float4*)(&kvs[kk][ty * 4]);
            float qa[4] = {qf.x, qf.y, qf.z, qf.w};
            float ka[4] = {kf.x, kf.y, kf.z, kf.w};
#pragma unroll
            for (int i = 0; i < 4; i++)
#pragma unroll
                for (int j = 0; j < 4; j++)
                    acc[i][j] += ka[i] * qa[j];
        }
        __syncthreads();

#pragma unroll
        for (int i = 0; i < 4; i++)
#pragma unroll
            for (int j = 0; j < 4; j++) pacc[i][j] = acc[i][j];
        have_prev = 1;
    }

    // final epilogue (t = TT-1)
    {
        const int ptb = (TT - 1) * BB + b;
#pragma unroll
        for (int i = 0; i < 4; i++) {
            const int e = ty * 4 + i;
            float4 r;
#pragma unroll
            for (int j = 0; j < 4; j++) {
                float xx = pacc[i][j] * 0.125f;
                float vv = v[i][j];
                vv = vv + (xx - vv) * 0.5f;
                float s = (vv >= VTH) ? 1.f : 0.f;
                v[i][j] = (s != 0.f) ? 0.f : vv;
                ((float*)&r)[j] = s;
            }
            *(float4*)(g_Sa + ((size_t)ptb * CC + h * DD + e) * NN + n0 + tx * 4) = r;
        }
    }
}

// ---------------------------------------------------------------------------
extern "C" void kernel_launch(void* const* d_in, const int* in_sizes, int n_in,
                              void* d_out, int out_size)
{
    const float* x  = (const float*)d_in[0];
    const float* Wq = (const float*)d_in[1];
    const float* bq = (const float*)d_in[2];
    const float* Wk = (const float*)d_in[3];
    const float* bk = (const float*)d_in[4];
    const float* Wv = (const float*)d_in[5];
    const float* bv = (const float*)d_in[6];
    const float* Wp = (const float*)d_in[7];
    const float* bp = (const float*)d_in[8];
    float* out = (float*)d_out;

    void *pS, *pSa, *pWt;
    cudaGetSymbolAddress(&pS, g_S);
    cudaGetSymbolAddress(&pSa, g_Sa);
    cudaGetSymbolAddress(&pWt, g_Wt);

    const int GL_SMEM = (12288 + 16384) * 4;  // 114688 bytes (3 stages + Vs)
    cudaFuncSetAttribute(gemm_lif<0>, cudaFuncAttributeMaxDynamicSharedMemorySize, GL_SMEM);
    cudaFuncSetAttribute(gemm_lif<1>, cudaFuncAttributeMaxDynamicSharedMemorySize, GL_SMEM);

    // 1. one-shot weight transpose (Wt[c][o])
    wtrans_kernel<<<dim3(16, 16, 4), 256>>>(Wq, Wk, Wv, Wp);
    // 2. fused QKV conv GEMM + LIF (q,k,v in one launch; bit-exact chains)
    gemm_lif<0><<<dim3(8, 4, 48), 256, GL_SMEM>>>(
        x, (const float*)pWt, 0, bq, bk, bv, nullptr, (float*)pS);
    // 3. fused pack + kv popcount (bit-exact integer counts)
    kv_pack_pop_kernel<<<TT * BB * HEADS, 256>>>();
    // 4. fused attention output + LIF (cp.async, Q double-buffered)
    attn_lif_kernel<<<dim3(NN / 64, BB * HEADS), 256>>>();
    // 5. fused proj conv GEMM + connecting LIF -> final spikes
    gemm_lif<1><<<dim3(8, 4, 16), 256, GL_SMEM>>>(
        (const float*)pSa, (const float*)pWt, 3, bp, bp, bp, x, out);
}